// round 15
// baseline (speedup 1.0000x reference)
#include <cuda_runtime.h>
#include <cuda_fp16.h>
#include <math.h>

#define NNODES 200000
#define NB     1024
#define NH     256
#define NH4    64
#define G3H    768
#define NOUT   128
#define CH     256      // nodes per pool chunk
#define NSLOT  8

#define GS     80                     // packed smem row stride (words)
#define GEMM_SMEM_BYTES (2 * 2 * 64 * GS * 4)   // 2 buffers x (As+Bs) x 64 x GS

// ---------------- scratch ----------------
__device__ __align__(16) __half g_x16[(size_t)NNODES * NH];   // fp16 copy of x
__device__ __align__(16) float g_wsrc[NH];
__device__ __align__(16) float g_wdst[NH];
__device__ __align__(16) float g_asrc[NNODES];
__device__ __align__(16) float g_out[NB * NH];
__device__ __align__(16) float g_sacc[NB * NH + NB];   // last NB floats = dsum
__device__ __align__(16) float g_h[NB * NH];
__device__ __align__(16) float g_gi[NB * G3H];
__device__ __align__(16) float g_gh[NB * G3H];
// pre-split tf32 weights (hi/lo)
__device__ __align__(16) unsigned g_WTH[NH * NH],      g_WTL[NH * NH];
__device__ __align__(16) unsigned g_WlinTH[NOUT * NH], g_WlinTL[NOUT * NH];
__device__ __align__(16) unsigned g_WihH[G3H * NH],    g_WihL[G3H * NH];
__device__ __align__(16) unsigned g_WhhH[G3H * NH],    g_WhhL[G3H * NH];

// ---------------- helpers ----------------
__device__ __forceinline__ float warp_sum(float v) {
#pragma unroll
    for (int off = 16; off; off >>= 1) v += __shfl_xor_sync(0xffffffffu, v, off);
    return v;
}
__device__ __forceinline__ float sigmoidf_(float x) { return 1.0f / (1.0f + expf(-x)); }
__device__ __forceinline__ float dot4(float4 a, float4 b) {
    return a.x * b.x + a.y * b.y + a.z * b.z + a.w * b.w;
}
__device__ __forceinline__ unsigned to_tf32(float x) {
    unsigned r;
    asm("cvt.rna.tf32.f32 %0, %1;" : "=r"(r) : "f"(x));
    return r;
}
__device__ __forceinline__ void split_tf32(float v, unsigned& hi, unsigned& lo) {
    hi = to_tf32(v);
    lo = to_tf32(v - __uint_as_float(hi));
}
__device__ __forceinline__ void mma_tf32(float* c, const unsigned* a, const unsigned* b) {
    asm volatile(
        "mma.sync.aligned.m16n8k8.row.col.f32.tf32.tf32.f32 "
        "{%0,%1,%2,%3}, {%4,%5,%6,%7}, {%8,%9}, {%0,%1,%2,%3};"
        : "+f"(c[0]), "+f"(c[1]), "+f"(c[2]), "+f"(c[3])
        : "r"(a[0]), "r"(a[1]), "r"(a[2]), "r"(a[3]), "r"(b[0]), "r"(b[1]));
}

// ------ prep: watt[0,64) + zero[64,192) + transpose-split[192,320) + split[320,704)
__global__ void prep_kernel(const float* __restrict__ W,
                            const float* __restrict__ att_src,
                            const float* __restrict__ att_dst,
                            const float* __restrict__ Wlin,
                            const float* __restrict__ W_ih,
                            const float* __restrict__ W_hh) {
    int bid = blockIdx.x;
    int tid = threadIdx.x;
    if (bid < 64) {
        int g = (bid * 256 + tid) >> 5;
        int l = tid & 31;
        int row = g & (NH - 1);
        bool isdst = g >= NH;
        const float4* Wr = reinterpret_cast<const float4*>(W + (size_t)row * NH);
        const float4* av = reinterpret_cast<const float4*>(isdst ? att_dst : att_src);
        float p = dot4(Wr[l], av[l]) + dot4(Wr[32 + l], av[32 + l]);
        p = warp_sum(p);
        if (l == 0) (isdst ? g_wdst : g_wsrc)[row] = p;
    } else if (bid < 192) {
        int idx = (bid - 64) * 256 + tid;
        int stride = 128 * 256;
        float4 z = make_float4(0.f, 0.f, 0.f, 0.f);
        float4* o = reinterpret_cast<float4*>(g_out);
        for (int i = idx; i < NB * NH / 4; i += stride) o[i] = z;
        float4* s = reinterpret_cast<float4*>(g_sacc);
        for (int i = idx; i < (NB * NH + NB) / 4; i += stride) s[i] = z;
    } else if (bid < 320) {
        // transpose + split: W -> WTH/WTL, Wlin -> WlinTH/WlinTL
        __shared__ float tile[32][33];
        int b = bid - 192;
        int z = b >> 6;
        int bx = (b & 7) * 32, by = ((b >> 3) & 7) * 32;
        const float* src = z ? Wlin : W;
        unsigned* dH = z ? g_WlinTH : g_WTH;
        unsigned* dL = z ? g_WlinTL : g_WTL;
        int C = z ? NOUT : NH;
        if (bx >= C) return;
        int tx = tid & 31, ty = tid >> 5;
#pragma unroll
        for (int j = 0; j < 32; j += 8)
            tile[ty + j][tx] = src[(size_t)(by + ty + j) * C + bx + tx];
        __syncthreads();
#pragma unroll
        for (int j = 0; j < 32; j += 8) {
            float v = tile[tx][ty + j];
            unsigned hv, lv;
            split_tf32(v, hv, lv);
            dH[(size_t)(bx + ty + j) * NH + by + tx] = hv;
            dL[(size_t)(bx + ty + j) * NH + by + tx] = lv;
        }
    } else {
        // elementwise split of W_ih / W_hh (row-major [G3H, NH])
        int idx = (bid - 320) * 256 + tid;      // float4 index, 2*49152 total
        const float4* src;
        unsigned *dH, *dL;
        if (idx < G3H * NH / 4) {
            src = reinterpret_cast<const float4*>(W_ih);
            dH = g_WihH; dL = g_WihL;
        } else {
            idx -= G3H * NH / 4;
            src = reinterpret_cast<const float4*>(W_hh);
            dH = g_WhhH; dL = g_WhhL;
        }
        float4 v = src[idx];
        uint4 hv, lv;
        split_tf32(v.x, hv.x, lv.x);
        split_tf32(v.y, hv.y, lv.y);
        split_tf32(v.z, hv.z, lv.z);
        split_tf32(v.w, hv.w, lv.w);
        *reinterpret_cast<uint4*>(&dH[(size_t)idx * 4]) = hv;
        *reinterpret_cast<uint4*>(&dL[(size_t)idx * 4]) = lv;
    }
}

// flush helpers
__device__ __forceinline__ void flushA(float* dst, int l, float4 a0, float4 a1) {
    float* p = dst + l * 4;
    atomicAdd(p + 0, a0.x); atomicAdd(p + 1, a0.y);
    atomicAdd(p + 2, a0.z); atomicAdd(p + 3, a0.w);
    p += 128;
    atomicAdd(p + 0, a1.x); atomicAdd(p + 1, a1.y);
    atomicAdd(p + 2, a1.z); atomicAdd(p + 3, a1.w);
}
__device__ __forceinline__ void flushC(float* dst, int l, const float* a) {
    float* p = dst + l * 8;
#pragma unroll
    for (int j = 0; j < 8; j++) atomicAdd(p + j, a[j]);
}

// ---------------- phase A: sum-pool + asrc + fp16 conversion ----------------
__global__ void __launch_bounds__(256, 6)
phaseA_kernel(const float4* __restrict__ x4, const int* __restrict__ batch, int n) {
    int base = blockIdx.x * CH;
    int tid = threadIdx.x, w = tid >> 5, l = tid & 31;
    __shared__ float sacc[NSLOT][NH];
    for (int i = tid; i < NSLOT * NH; i += 256) (&sacc[0][0])[i] = 0.f;
    __syncthreads();
    int fg = batch[base];
    int lo = base + w * 32;
    int hi = min(base + (w + 1) * 32, n);

    const float4* wa = reinterpret_cast<const float4*>(g_wsrc);
    float4 w0 = wa[l], w1 = wa[32 + l];
    float4 a0 = make_float4(0.f, 0.f, 0.f, 0.f);
    float4 a1 = make_float4(0.f, 0.f, 0.f, 0.f);

    auto conv = [&](int i, float4 u0, float4 u1) {
        __half2 h00 = __floats2half2_rn(u0.x, u0.y), h01 = __floats2half2_rn(u0.z, u0.w);
        __half2 h10 = __floats2half2_rn(u1.x, u1.y), h11 = __floats2half2_rn(u1.z, u1.w);
        uint2 p0, p1;
        p0.x = *reinterpret_cast<unsigned*>(&h00); p0.y = *reinterpret_cast<unsigned*>(&h01);
        p1.x = *reinterpret_cast<unsigned*>(&h10); p1.y = *reinterpret_cast<unsigned*>(&h11);
        __half* dst = g_x16 + (size_t)i * NH;
        *reinterpret_cast<uint2*>(dst + l * 4) = p0;
        *reinterpret_cast<uint2*>(dst + 128 + l * 4) = p1;
    };
    auto add8 = [&](float4 u0, float4 u1) {
        a0.x += u0.x; a0.y += u0.y; a0.z += u0.z; a0.w += u0.w;
        a1.x += u1.x; a1.y += u1.y; a1.z += u1.z; a1.w += u1.w;
    };

    if (lo < hi) {
        int b0 = batch[lo], b1 = batch[hi - 1];
        if (b0 == b1) {
            int i = lo;
            for (; i + 4 <= hi; i += 4) {
                const float4* r = x4 + (size_t)i * NH4;
                float4 u0 = r[l],       u1 = r[32 + l];
                float4 v0 = r[64 + l],  v1 = r[96 + l];
                float4 s0 = r[128 + l], s1 = r[160 + l];
                float4 t0 = r[192 + l], t1 = r[224 + l];
                conv(i, u0, u1); conv(i + 1, v0, v1);
                conv(i + 2, s0, s1); conv(i + 3, t0, t1);
                add8(u0, u1); add8(v0, v1); add8(s0, s1); add8(t0, t1);
                float p0 = dot4(u0, w0) + dot4(u1, w1);
                float p1 = dot4(v0, w0) + dot4(v1, w1);
                float p2 = dot4(s0, w0) + dot4(s1, w1);
                float p3 = dot4(t0, w0) + dot4(t1, w1);
#pragma unroll
                for (int off = 16; off; off >>= 1) {
                    p0 += __shfl_xor_sync(0xffffffffu, p0, off);
                    p1 += __shfl_xor_sync(0xffffffffu, p1, off);
                    p2 += __shfl_xor_sync(0xffffffffu, p2, off);
                    p3 += __shfl_xor_sync(0xffffffffu, p3, off);
                }
                if (l == 0)
                    *reinterpret_cast<float4*>(&g_asrc[i]) = make_float4(p0, p1, p2, p3);
            }
            for (; i < hi; i++) {
                const float4* r = x4 + (size_t)i * NH4;
                float4 u0 = r[l], u1 = r[32 + l];
                conv(i, u0, u1);
                add8(u0, u1);
                float p = warp_sum(dot4(u0, w0) + dot4(u1, w1));
                if (l == 0) g_asrc[i] = p;
            }
            int slot = b0 - fg;
            flushA(slot < NSLOT ? &sacc[slot][0] : &g_out[(size_t)b0 * NH], l, a0, a1);
        } else {
            int cur = b0;
            for (int i = lo; i < hi; i++) {
                int bb = batch[i];
                if (bb != cur) {
                    int slot = cur - fg;
                    flushA(slot < NSLOT ? &sacc[slot][0] : &g_out[(size_t)cur * NH], l, a0, a1);
                    a0 = make_float4(0.f, 0.f, 0.f, 0.f);
                    a1 = make_float4(0.f, 0.f, 0.f, 0.f);
                    cur = bb;
                }
                const float4* r = x4 + (size_t)i * NH4;
                float4 u0 = r[l], u1 = r[32 + l];
                conv(i, u0, u1);
                add8(u0, u1);
                float p = warp_sum(dot4(u0, w0) + dot4(u1, w1));
                if (l == 0) g_asrc[i] = p;
            }
            int slot = cur - fg;
            flushA(slot < NSLOT ? &sacc[slot][0] : &g_out[(size_t)cur * NH], l, a0, a1);
        }
    }
    __syncthreads();
    int last = min(base + CH, n) - 1;
    int nspan = min(batch[last] - fg + 1, NSLOT);
    for (int s = 0; s < nspan; s++)
        atomicAdd(&g_out[(size_t)(fg + s) * NH + tid], sacc[s][tid]);
}

// ---------------- attention pool (fp16 x, fused adst, unnormalized + dsum) -------
__global__ void __launch_bounds__(256, 6)
attnpool_kernel(const int* __restrict__ batch, int n) {
    int base = blockIdx.x * CH;
    int tid = threadIdx.x, w = tid >> 5, l = tid & 31;
    __shared__ float sacc[NSLOT][NH];
    __shared__ float sds[NSLOT];
    for (int i = tid; i < NSLOT * NH; i += 256) (&sacc[0][0])[i] = 0.f;
    if (tid < NSLOT) sds[tid] = 0.f;
    __syncthreads();
    int fg = batch[base];
    int lo = base + w * 32;
    int hi = min(base + (w + 1) * 32, n);
    float* gdsum = g_sacc + (size_t)NB * NH;

    const float4* wd4 = reinterpret_cast<const float4*>(g_wdst);
    float4 d0 = wd4[2 * l], d1 = wd4[2 * l + 1];

    auto compute_adst = [&](int b) -> float {
        const float4* o4 = reinterpret_cast<const float4*>(g_out + (size_t)b * NH);
        return warp_sum(dot4(o4[2 * l], d0) + dot4(o4[2 * l + 1], d1));
    };
    auto acc8 = [&](uint4 v, float wgt, float* a) {
        __half2 h; float2 f;
        *reinterpret_cast<unsigned*>(&h) = v.x; f = __half22float2(h);
        a[0] += wgt * f.x; a[1] += wgt * f.y;
        *reinterpret_cast<unsigned*>(&h) = v.y; f = __half22float2(h);
        a[2] += wgt * f.x; a[3] += wgt * f.y;
        *reinterpret_cast<unsigned*>(&h) = v.z; f = __half22float2(h);
        a[4] += wgt * f.x; a[5] += wgt * f.y;
        *reinterpret_cast<unsigned*>(&h) = v.w; f = __half22float2(h);
        a[6] += wgt * f.x; a[7] += wgt * f.y;
    };

    float a[8];
#pragma unroll
    for (int j = 0; j < 8; j++) a[j] = 0.f;
    float ds = 0.f;

    if (lo < hi) {
        int b0 = batch[lo], b1 = batch[hi - 1];
        if (b0 == b1) {
            float adst = compute_adst(b0);
            int i = lo;
            for (; i + 8 <= hi; i += 8) {
                const uint4* r = reinterpret_cast<const uint4*>(g_x16 + (size_t)i * NH);
                uint4 v0 = r[l],       v1 = r[32 + l],  v2 = r[64 + l],  v3 = r[96 + l];
                uint4 v4 = r[128 + l], v5 = r[160 + l], v6 = r[192 + l], v7 = r[224 + l];
                const float4* ap = reinterpret_cast<const float4*>(&g_asrc[i]);
                float4 ea = ap[0], eb = ap[1];
                float g[8] = {ea.x + adst, ea.y + adst, ea.z + adst, ea.w + adst,
                              eb.x + adst, eb.y + adst, eb.z + adst, eb.w + adst};
#pragma unroll
                for (int u = 0; u < 8; u++) {
                    float e = g[u];
                    e = e > 0.f ? e : 0.01f * e;
                    g[u] = __expf(e);
                    ds += g[u];
                }
                acc8(v0, g[0], a); acc8(v1, g[1], a); acc8(v2, g[2], a); acc8(v3, g[3], a);
                acc8(v4, g[4], a); acc8(v5, g[5], a); acc8(v6, g[6], a); acc8(v7, g[7], a);
            }
            for (; i < hi; i++) {
                float e = g_asrc[i] + adst;
                e = e > 0.f ? e : 0.01f * e;
                float wgt = __expf(e);
                ds += wgt;
                const uint4* r = reinterpret_cast<const uint4*>(g_x16 + (size_t)i * NH);
                acc8(r[l], wgt, a);
            }
            int slot = b0 - fg;
            if (slot < NSLOT) {
                flushC(&sacc[slot][0], l, a);
                if (l == 0) atomicAdd(&sds[slot], ds);
            } else {
                flushC(&g_sacc[(size_t)b0 * NH], l, a);
                if (l == 0) atomicAdd(&gdsum[b0], ds);
            }
        } else {
            int cur = b0;
            float adst = compute_adst(cur);
            for (int i = lo; i < hi; i++) {
                int bb = batch[i];
                if (bb != cur) {
                    int slot = cur - fg;
                    if (slot < NSLOT) {
                        flushC(&sacc[slot][0], l, a);
                        if (l == 0) atomicAdd(&sds[slot], ds);
                    } else {
                        flushC(&g_sacc[(size_t)cur * NH], l, a);
                        if (l == 0) atomicAdd(&gdsum[cur], ds);
                    }
#pragma unroll
                    for (int j = 0; j < 8; j++) a[j] = 0.f;
                    ds = 0.f;
                    cur = bb;
                    adst = compute_adst(cur);
                }
                float e = g_asrc[i] + adst;
                e = e > 0.f ? e : 0.01f * e;
                float wgt = __expf(e);
                ds += wgt;
                const uint4* r = reinterpret_cast<const uint4*>(g_x16 + (size_t)i * NH);
                acc8(r[l], wgt, a);
            }
            int slot = cur - fg;
            if (slot < NSLOT) {
                flushC(&sacc[slot][0], l, a);
                if (l == 0) atomicAdd(&sds[slot], ds);
            } else {
                flushC(&g_sacc[(size_t)cur * NH], l, a);
                if (l == 0) atomicAdd(&gdsum[cur], ds);
            }
        }
    }
    __syncthreads();
    int last = min(base + CH, n) - 1;
    int nspan = min(batch[last] - fg + 1, NSLOT);
    for (int s = 0; s < nspan; s++)
        atomicAdd(&g_sacc[(size_t)(fg + s) * NH + tid], sacc[s][tid]);
    if (tid < nspan) atomicAdd(&gdsum[fg + tid], sds[tid]);
}

// ------ 3xTF32 GEMM, NT, pre-split B, pair-packed interleaved smem + dbl buffer --
// smem per buffer: As[64][GS] (H/L interleaved), Bs[64][GS]. value k, part p(0=H,1=L)
// stored at column 2*((k&~7) + 2*(k&3) + ((k>>2)&1)) + p. One LDS.128 = full frag pair.
template <int ACT, int SCALE>
__device__ __forceinline__ void gemm_nt(unsigned* dsm,
                                        const float* __restrict__ A,
                                        const unsigned* __restrict__ BH,
                                        const unsigned* __restrict__ BL,
                                        const float* __restrict__ bias, float* __restrict__ C,
                                        int N, int bm, int bn) {
    const int K = 256;
    const int BUF = 2 * 64 * GS;          // words per buffer (As + Bs)
    int tid = threadIdx.x;
    int lane = tid & 31, wp = tid >> 5;   // 8 warps
    int wm = wp >> 1, wn = wp & 1;        // 4 x 2
    int g = lane >> 2, t = lane & 3;
    float acc[4][4];
#pragma unroll
    for (int j = 0; j < 4; j++)
#pragma unroll
        for (int r = 0; r < 4; r++) acc[j][r] = 0.f;

    // prefetch registers
    float4 pva[2];
    uint4  pvh[2], pvl[2];
    int m0 = tid >> 3, kq = tid & 7;           // m0 0..31
    int m1 = m0 + 32;
    size_t aoff0 = (size_t)(bm + m0) * K + kq * 4;
    size_t aoff1 = (size_t)(bm + m1) * K + kq * 4;
    size_t boff0 = (size_t)(bn + m0) * K + kq * 4;
    size_t boff1 = (size_t)(bn + m1) * K + kq * 4;
    int c0 = ((kq >> 1) << 4) + ((kq & 1) << 1);   // packed column base for this kq

    auto fetch = [&](int k0) {
        pva[0] = *reinterpret_cast<const float4*>(&A[aoff0 + k0]);
        pva[1] = *reinterpret_cast<const float4*>(&A[aoff1 + k0]);
        pvh[0] = *reinterpret_cast<const uint4*>(&BH[boff0 + k0]);
        pvh[1] = *reinterpret_cast<const uint4*>(&BH[boff1 + k0]);
        pvl[0] = *reinterpret_cast<const uint4*>(&BL[boff0 + k0]);
        pvl[1] = *reinterpret_cast<const uint4*>(&BL[boff1 + k0]);
    };
    auto stage = [&](int buf) {
        unsigned* As = dsm + buf * BUF;
        unsigned* Bs = As + 64 * GS;
#pragma unroll
        for (int r = 0; r < 2; r++) {
            int m = r ? m1 : m0;
            unsigned* ap = As + m * GS + c0;
            float4 va = pva[r];
            unsigned h, l;
            split_tf32(va.x, h, l); *reinterpret_cast<uint2*>(ap + 0)  = make_uint2(h, l);
            split_tf32(va.y, h, l); *reinterpret_cast<uint2*>(ap + 4)  = make_uint2(h, l);
            split_tf32(va.z, h, l); *reinterpret_cast<uint2*>(ap + 8)  = make_uint2(h, l);
            split_tf32(va.w, h, l); *reinterpret_cast<uint2*>(ap + 12) = make_uint2(h, l);
            unsigned* bp = Bs + m * GS + c0;
            uint4 vh = pvh[r]; uint4 vl = pvl[r];
            *reinterpret_cast<uint2*>(bp + 0)  = make_uint2(vh.x, vl.x);
            *reinterpret_cast<uint2*>(bp + 4)  = make_uint2(vh.y, vl.y);
            *reinterpret_cast<uint2*>(bp + 8)  = make_uint2(vh.z, vl.z);
            *reinterpret_cast<uint2*>(bp + 12) = make_uint2(vh.w, vl.w);
        }
    };

    fetch(0);
    stage(0);
    __syncthreads();
    for (int it = 0; it < 8; it++) {
        int cur = it & 1;
        if (it < 7) fetch((it + 1) * 32);     // loads fly during compute below
        unsigned* As = dsm + cur * BUF;
        unsigned* Bs = As + 64 * GS;
        int r0 = wm * 16 + g;
        unsigned* arow0 = As + r0 * GS + 4 * t;
        unsigned* arow1 = As + (r0 + 8) * GS + 4 * t;
#pragma unroll
        for (int ks = 0; ks < 4; ks++) {
            int cb = 16 * ks;
            uint4 pa0 = *reinterpret_cast<uint4*>(arow0 + cb);
            uint4 pa1 = *reinterpret_cast<uint4*>(arow1 + cb);
            unsigned aH[4] = {pa0.x, pa1.x, pa0.z, pa1.z};
            unsigned aL[4] = {pa0.y, pa1.y, pa0.w, pa1.w};
#pragma unroll
            for (int tj = 0; tj < 4; tj++) {
                int nr = wn * 32 + tj * 8 + g;
                uint4 pb = *reinterpret_cast<uint4*>(Bs + nr * GS + cb + 4 * t);
                unsigned bH[2] = {pb.x, pb.z};
                unsigned bL[2] = {pb.y, pb.w};
                mma_tf32(acc[tj], aH, bH);
                mma_tf32(acc[tj], aH, bL);
                mma_tf32(acc[tj], aL, bH);
            }
        }
        if (it < 7) stage(1 - cur);
        __syncthreads();
    }
    const float* dsum = g_sacc + (size_t)NB * NH;
    {
        int r0 = bm + wm * 16 + g;
        float invl = 1.f, invh = 1.f;
        if (SCALE) {
            float dv0 = dsum[r0];
            float dv1 = dsum[r0 + 8];
            invl = dv0 > 0.f ? 1.f / dv0 : 0.f;
            invh = dv1 > 0.f ? 1.f / dv1 : 0.f;
        }
#pragma unroll
        for (int tj = 0; tj < 4; tj++) {
            int col = bn + wn * 32 + tj * 8 + 2 * t;
            float b0 = bias[col], b1 = bias[col + 1];
            float c0v = acc[tj][0] * invl + b0;
            float c1v = acc[tj][1] * invl + b1;
            float c2v = acc[tj][2] * invh + b0;
            float c3v = acc[tj][3] * invh + b1;
            if (ACT) {
                c0v = c0v > 0.f ? c0v : expm1f(c0v);
                c1v = c1v > 0.f ? c1v : expm1f(c1v);
                c2v = c2v > 0.f ? c2v : expm1f(c2v);
                c3v = c3v > 0.f ? c3v : expm1f(c3v);
            }
            *reinterpret_cast<float2*>(&C[(size_t)r0 * N + col]) = make_float2(c0v, c1v);
            *reinterpret_cast<float2*>(&C[(size_t)(r0 + 8) * N + col]) = make_float2(c2v, c3v);
        }
    }
}

// h = elu((sacc/dsum) @ W + bias_gat) [64 blocks] + gh = out @ W_hh^T + b_hh [192]
__global__ void __launch_bounds__(256)
gemm_h_gh_kernel(const float* __restrict__ bias_gat, const float* __restrict__ b_hh) {
    extern __shared__ __align__(16) unsigned dsm[];
    int bid = blockIdx.x;
    if (bid < 64)
        gemm_nt<1, 1>(dsm, g_sacc, g_WTH, g_WTL, bias_gat, g_h, NH,
                      (bid >> 2) * 64, (bid & 3) * 64);
    else {
        int b2 = bid - 64;
        gemm_nt<0, 0>(dsm, g_out, g_WhhH, g_WhhL, b_hh, g_gh, G3H,
                      (b2 / 12) * 64, (b2 % 12) * 64);
    }
}

__global__ void __launch_bounds__(256)
gemm_gi_kernel(const float* __restrict__ b_ih) {
    extern __shared__ __align__(16) unsigned dsm[];
    gemm_nt<0, 0>(dsm, g_h, g_WihH, g_WihL, b_ih, g_gi, G3H,
                  (blockIdx.x / 12) * 64, (blockIdx.x % 12) * 64);
}

__global__ void __launch_bounds__(256)
gemm_final_kernel(const float* __restrict__ b_lin, float* __restrict__ out) {
    extern __shared__ __align__(16) unsigned dsm[];
    gemm_nt<0, 0>(dsm, g_out, g_WlinTH, g_WlinTL, b_lin, out, NOUT,
                  (blockIdx.x >> 1) * 64, (blockIdx.x & 1) * 64);
}

// ------------- GRU elementwise update (in place) + zero sacc for next t ----------
__global__ void gru_kernel() {
    int idx = blockIdx.x * blockDim.x + threadIdx.x;   // 256 blocks x 256 = 65536
    int b = idx >> 6, h4 = idx & 63;
    const float4* gi4 = reinterpret_cast<const float4*>(g_gi) + (size_t)b * (G3H / 4);
    const float4* gh4 = reinterpret_cast<const float4*>(g_gh) + (size_t)b * (G3H / 4);
    float4 gir = gi4[h4], giz = gi4[64 + h4], gin = gi4[128 + h4];
    float4 ghr = gh4[h4], ghz = gh4[64 + h4], ghn = gh4[128 + h4];
    float4* out4 = reinterpret_cast<float4*>(g_out) + idx;
    float4 o = *out4;
    float4 res;
    {
        float r = sigmoidf_(gir.x + ghr.x), z = sigmoidf_(giz.x + ghz.x);
        float nn = tanhf(gin.x + r * ghn.x);
        float v = (1.f - z) * nn + z * o.x; res.x = v * sigmoidf_(v);
    }
    {
        float r = sigmoidf_(gir.y + ghr.y), z = sigmoidf_(giz.y + ghz.y);
        float nn = tanhf(gin.y + r * ghn.y);
        float v = (1.f - z) * nn + z * o.y; res.y = v * sigmoidf_(v);
    }
    {
        float r = sigmoidf_(gir.z + ghr.z), z = sigmoidf_(giz.z + ghz.z);
        float nn = tanhf(gin.z + r * ghn.z);
        float v = (1.f - z) * nn + z * o.z; res.z = v * sigmoidf_(v);
    }
    {
        float r = sigmoidf_(gir.w + ghr.w), z = sigmoidf_(giz.w + ghz.w);
        float nn = tanhf(gin.w + r * ghn.w);
        float v = (1.f - z) * nn + z * o.w; res.w = v * sigmoidf_(v);
    }
    *out4 = res;
    float4 zz = make_float4(0.f, 0.f, 0.f, 0.f);
    float4* s4 = reinterpret_cast<float4*>(g_sacc);
    for (int i = idx; i < (NB * NH + NB) / 4; i += 65536) s4[i] = zz;
}

// ---------------- launch (single stream) ----------------
extern "C" void kernel_launch(void* const* d_in, const int* in_sizes, int n_in,
                              void* d_out, int out_size) {
    const float* x        = (const float*)d_in[0];
    const int*   batch    = (const int*)d_in[1];
    const float* W        = (const float*)d_in[2];
    const float* att_src  = (const float*)d_in[3];
    const float* att_dst  = (const float*)d_in[4];
    const float* bias_gat = (const float*)d_in[5];
    const float* W_ih     = (const float*)d_in[6];
    const float* W_hh     = (const float*)d_in[7];
    const float* b_ih     = (const float*)d_in[8];
    const float* b_hh     = (const float*)d_in[9];
    const float* W_lin    = (const float*)d_in[10];
    const float* b_lin    = (const float*)d_in[11];
    float*       out      = (float*)d_out;

    const int n = in_sizes[1];
    const int nch = (n + CH - 1) / CH;
    const float4* x4 = reinterpret_cast<const float4*>(x);

    // raise dynamic smem limit for the GEMM kernels (host-side attr, capture-safe)
    cudaFuncSetAttribute(gemm_h_gh_kernel,
                         cudaFuncAttributeMaxDynamicSharedMemorySize, GEMM_SMEM_BYTES);
    cudaFuncSetAttribute(gemm_gi_kernel,
                         cudaFuncAttributeMaxDynamicSharedMemorySize, GEMM_SMEM_BYTES);
    cudaFuncSetAttribute(gemm_final_kernel,
                         cudaFuncAttributeMaxDynamicSharedMemorySize, GEMM_SMEM_BYTES);

    prep_kernel<<<704, 256>>>(W, att_src, att_dst, W_lin, W_ih, W_hh);
    phaseA_kernel<<<nch, 256>>>(x4, batch, n);

    for (int t = 0; t < 2; t++) {
        attnpool_kernel<<<nch, 256>>>(batch, n);
        gemm_h_gh_kernel<<<256, 256, GEMM_SMEM_BYTES>>>(bias_gat, b_hh);
        gemm_gi_kernel<<<192, 256, GEMM_SMEM_BYTES>>>(b_ih);
        gru_kernel<<<256, 256>>>();
    }

    gemm_final_kernel<<<32, 256, GEMM_SMEM_BYTES>>>(b_lin, out);
}

// round 16
// speedup vs baseline: 1.1133x; 1.1133x over previous
#include <cuda_runtime.h>
#include <cuda_fp16.h>
#include <math.h>

#define NNODES 200000
#define NB     1024
#define NH     256
#define NH4    64
#define G3H    768
#define NOUT   128
#define CH     256      // nodes per pool chunk
#define NSLOT  8

#define GBUF   (4 * 64 * 36)                    // words per buffer: AsH,AsL,BsH,BsL [64][36]
#define GEMM_SMEM_BYTES (2 * GBUF * 4)          // two buffers = 73728 B

// ---------------- scratch ----------------
__device__ __align__(16) __half g_x16[(size_t)NNODES * NH];   // fp16 copy of x
__device__ __align__(16) float g_wsrc[NH];
__device__ __align__(16) float g_wdst[NH];
__device__ __align__(16) float g_asrc[NNODES];
__device__ __align__(16) float g_out[NB * NH];
__device__ __align__(16) float g_sacc[NB * NH + NB];   // last NB floats = dsum
__device__ __align__(16) float g_h[NB * NH];
__device__ __align__(16) float g_gi[NB * G3H];
__device__ __align__(16) float g_gh[NB * G3H];
// pre-split tf32 weights (hi/lo)
__device__ __align__(16) unsigned g_WTH[NH * NH],      g_WTL[NH * NH];
__device__ __align__(16) unsigned g_WlinTH[NOUT * NH], g_WlinTL[NOUT * NH];
__device__ __align__(16) unsigned g_WihH[G3H * NH],    g_WihL[G3H * NH];
__device__ __align__(16) unsigned g_WhhH[G3H * NH],    g_WhhL[G3H * NH];

// ---------------- helpers ----------------
__device__ __forceinline__ float warp_sum(float v) {
#pragma unroll
    for (int off = 16; off; off >>= 1) v += __shfl_xor_sync(0xffffffffu, v, off);
    return v;
}
__device__ __forceinline__ float sigmoidf_(float x) { return 1.0f / (1.0f + expf(-x)); }
__device__ __forceinline__ float dot4(float4 a, float4 b) {
    return a.x * b.x + a.y * b.y + a.z * b.z + a.w * b.w;
}
__device__ __forceinline__ unsigned to_tf32(float x) {
    unsigned r;
    asm("cvt.rna.tf32.f32 %0, %1;" : "=r"(r) : "f"(x));
    return r;
}
__device__ __forceinline__ void split_tf32(float v, unsigned& hi, unsigned& lo) {
    hi = to_tf32(v);
    lo = to_tf32(v - __uint_as_float(hi));
}
__device__ __forceinline__ void mma_tf32(float* c, const unsigned* a, const unsigned* b) {
    asm volatile(
        "mma.sync.aligned.m16n8k8.row.col.f32.tf32.tf32.f32 "
        "{%0,%1,%2,%3}, {%4,%5,%6,%7}, {%8,%9}, {%0,%1,%2,%3};"
        : "+f"(c[0]), "+f"(c[1]), "+f"(c[2]), "+f"(c[3])
        : "r"(a[0]), "r"(a[1]), "r"(a[2]), "r"(a[3]), "r"(b[0]), "r"(b[1]));
}

// ------ prep: watt[0,64) + zero[64,192) + transpose-split[192,320) + split[320,704)
__global__ void prep_kernel(const float* __restrict__ W,
                            const float* __restrict__ att_src,
                            const float* __restrict__ att_dst,
                            const float* __restrict__ Wlin,
                            const float* __restrict__ W_ih,
                            const float* __restrict__ W_hh) {
    int bid = blockIdx.x;
    int tid = threadIdx.x;
    if (bid < 64) {
        int g = (bid * 256 + tid) >> 5;
        int l = tid & 31;
        int row = g & (NH - 1);
        bool isdst = g >= NH;
        const float4* Wr = reinterpret_cast<const float4*>(W + (size_t)row * NH);
        const float4* av = reinterpret_cast<const float4*>(isdst ? att_dst : att_src);
        float p = dot4(Wr[l], av[l]) + dot4(Wr[32 + l], av[32 + l]);
        p = warp_sum(p);
        if (l == 0) (isdst ? g_wdst : g_wsrc)[row] = p;
    } else if (bid < 192) {
        int idx = (bid - 64) * 256 + tid;
        int stride = 128 * 256;
        float4 z = make_float4(0.f, 0.f, 0.f, 0.f);
        float4* o = reinterpret_cast<float4*>(g_out);
        for (int i = idx; i < NB * NH / 4; i += stride) o[i] = z;
        float4* s = reinterpret_cast<float4*>(g_sacc);
        for (int i = idx; i < (NB * NH + NB) / 4; i += stride) s[i] = z;
    } else if (bid < 320) {
        // transpose + split: W -> WTH/WTL, Wlin -> WlinTH/WlinTL
        __shared__ float tile[32][33];
        int b = bid - 192;
        int z = b >> 6;
        int bx = (b & 7) * 32, by = ((b >> 3) & 7) * 32;
        const float* src = z ? Wlin : W;
        unsigned* dH = z ? g_WlinTH : g_WTH;
        unsigned* dL = z ? g_WlinTL : g_WTL;
        int C = z ? NOUT : NH;
        if (bx >= C) return;
        int tx = tid & 31, ty = tid >> 5;
#pragma unroll
        for (int j = 0; j < 32; j += 8)
            tile[ty + j][tx] = src[(size_t)(by + ty + j) * C + bx + tx];
        __syncthreads();
#pragma unroll
        for (int j = 0; j < 32; j += 8) {
            float v = tile[tx][ty + j];
            unsigned hv, lv;
            split_tf32(v, hv, lv);
            dH[(size_t)(bx + ty + j) * NH + by + tx] = hv;
            dL[(size_t)(bx + ty + j) * NH + by + tx] = lv;
        }
    } else {
        // elementwise split of W_ih / W_hh (row-major [G3H, NH])
        int idx = (bid - 320) * 256 + tid;      // float4 index, 2*49152 total
        const float4* src;
        unsigned *dH, *dL;
        if (idx < G3H * NH / 4) {
            src = reinterpret_cast<const float4*>(W_ih);
            dH = g_WihH; dL = g_WihL;
        } else {
            idx -= G3H * NH / 4;
            src = reinterpret_cast<const float4*>(W_hh);
            dH = g_WhhH; dL = g_WhhL;
        }
        float4 v = src[idx];
        uint4 hv, lv;
        split_tf32(v.x, hv.x, lv.x);
        split_tf32(v.y, hv.y, lv.y);
        split_tf32(v.z, hv.z, lv.z);
        split_tf32(v.w, hv.w, lv.w);
        *reinterpret_cast<uint4*>(&dH[(size_t)idx * 4]) = hv;
        *reinterpret_cast<uint4*>(&dL[(size_t)idx * 4]) = lv;
    }
}

// flush helpers
__device__ __forceinline__ void flushA(float* dst, int l, float4 a0, float4 a1) {
    float* p = dst + l * 4;
    atomicAdd(p + 0, a0.x); atomicAdd(p + 1, a0.y);
    atomicAdd(p + 2, a0.z); atomicAdd(p + 3, a0.w);
    p += 128;
    atomicAdd(p + 0, a1.x); atomicAdd(p + 1, a1.y);
    atomicAdd(p + 2, a1.z); atomicAdd(p + 3, a1.w);
}
__device__ __forceinline__ void flushC(float* dst, int l, const float* a) {
    float* p = dst + l * 8;
#pragma unroll
    for (int j = 0; j < 8; j++) atomicAdd(p + j, a[j]);
}

// ---------------- phase A: sum-pool + asrc + fp16 conversion ----------------
__global__ void __launch_bounds__(256, 6)
phaseA_kernel(const float4* __restrict__ x4, const int* __restrict__ batch, int n) {
    int base = blockIdx.x * CH;
    int tid = threadIdx.x, w = tid >> 5, l = tid & 31;
    __shared__ float sacc[NSLOT][NH];
    for (int i = tid; i < NSLOT * NH; i += 256) (&sacc[0][0])[i] = 0.f;
    __syncthreads();
    int fg = batch[base];
    int lo = base + w * 32;
    int hi = min(base + (w + 1) * 32, n);

    const float4* wa = reinterpret_cast<const float4*>(g_wsrc);
    float4 w0 = wa[l], w1 = wa[32 + l];
    float4 a0 = make_float4(0.f, 0.f, 0.f, 0.f);
    float4 a1 = make_float4(0.f, 0.f, 0.f, 0.f);

    auto conv = [&](int i, float4 u0, float4 u1) {
        __half2 h00 = __floats2half2_rn(u0.x, u0.y), h01 = __floats2half2_rn(u0.z, u0.w);
        __half2 h10 = __floats2half2_rn(u1.x, u1.y), h11 = __floats2half2_rn(u1.z, u1.w);
        uint2 p0, p1;
        p0.x = *reinterpret_cast<unsigned*>(&h00); p0.y = *reinterpret_cast<unsigned*>(&h01);
        p1.x = *reinterpret_cast<unsigned*>(&h10); p1.y = *reinterpret_cast<unsigned*>(&h11);
        __half* dst = g_x16 + (size_t)i * NH;
        *reinterpret_cast<uint2*>(dst + l * 4) = p0;
        *reinterpret_cast<uint2*>(dst + 128 + l * 4) = p1;
    };
    auto add8 = [&](float4 u0, float4 u1) {
        a0.x += u0.x; a0.y += u0.y; a0.z += u0.z; a0.w += u0.w;
        a1.x += u1.x; a1.y += u1.y; a1.z += u1.z; a1.w += u1.w;
    };

    if (lo < hi) {
        int b0 = batch[lo], b1 = batch[hi - 1];
        if (b0 == b1) {
            int i = lo;
            for (; i + 4 <= hi; i += 4) {
                const float4* r = x4 + (size_t)i * NH4;
                float4 u0 = r[l],       u1 = r[32 + l];
                float4 v0 = r[64 + l],  v1 = r[96 + l];
                float4 s0 = r[128 + l], s1 = r[160 + l];
                float4 t0 = r[192 + l], t1 = r[224 + l];
                conv(i, u0, u1); conv(i + 1, v0, v1);
                conv(i + 2, s0, s1); conv(i + 3, t0, t1);
                add8(u0, u1); add8(v0, v1); add8(s0, s1); add8(t0, t1);
                float p0 = dot4(u0, w0) + dot4(u1, w1);
                float p1 = dot4(v0, w0) + dot4(v1, w1);
                float p2 = dot4(s0, w0) + dot4(s1, w1);
                float p3 = dot4(t0, w0) + dot4(t1, w1);
#pragma unroll
                for (int off = 16; off; off >>= 1) {
                    p0 += __shfl_xor_sync(0xffffffffu, p0, off);
                    p1 += __shfl_xor_sync(0xffffffffu, p1, off);
                    p2 += __shfl_xor_sync(0xffffffffu, p2, off);
                    p3 += __shfl_xor_sync(0xffffffffu, p3, off);
                }
                if (l == 0)
                    *reinterpret_cast<float4*>(&g_asrc[i]) = make_float4(p0, p1, p2, p3);
            }
            for (; i < hi; i++) {
                const float4* r = x4 + (size_t)i * NH4;
                float4 u0 = r[l], u1 = r[32 + l];
                conv(i, u0, u1);
                add8(u0, u1);
                float p = warp_sum(dot4(u0, w0) + dot4(u1, w1));
                if (l == 0) g_asrc[i] = p;
            }
            int slot = b0 - fg;
            flushA(slot < NSLOT ? &sacc[slot][0] : &g_out[(size_t)b0 * NH], l, a0, a1);
        } else {
            int cur = b0;
            for (int i = lo; i < hi; i++) {
                int bb = batch[i];
                if (bb != cur) {
                    int slot = cur - fg;
                    flushA(slot < NSLOT ? &sacc[slot][0] : &g_out[(size_t)cur * NH], l, a0, a1);
                    a0 = make_float4(0.f, 0.f, 0.f, 0.f);
                    a1 = make_float4(0.f, 0.f, 0.f, 0.f);
                    cur = bb;
                }
                const float4* r = x4 + (size_t)i * NH4;
                float4 u0 = r[l], u1 = r[32 + l];
                conv(i, u0, u1);
                add8(u0, u1);
                float p = warp_sum(dot4(u0, w0) + dot4(u1, w1));
                if (l == 0) g_asrc[i] = p;
            }
            int slot = cur - fg;
            flushA(slot < NSLOT ? &sacc[slot][0] : &g_out[(size_t)cur * NH], l, a0, a1);
        }
    }
    __syncthreads();
    int last = min(base + CH, n) - 1;
    int nspan = min(batch[last] - fg + 1, NSLOT);
    for (int s = 0; s < nspan; s++)
        atomicAdd(&g_out[(size_t)(fg + s) * NH + tid], sacc[s][tid]);
}

// ---------------- attention pool (fp16 x, fused adst, unnormalized + dsum) -------
__global__ void __launch_bounds__(256, 6)
attnpool_kernel(const int* __restrict__ batch, int n) {
    int base = blockIdx.x * CH;
    int tid = threadIdx.x, w = tid >> 5, l = tid & 31;
    __shared__ float sacc[NSLOT][NH];
    __shared__ float sds[NSLOT];
    for (int i = tid; i < NSLOT * NH; i += 256) (&sacc[0][0])[i] = 0.f;
    if (tid < NSLOT) sds[tid] = 0.f;
    __syncthreads();
    int fg = batch[base];
    int lo = base + w * 32;
    int hi = min(base + (w + 1) * 32, n);
    float* gdsum = g_sacc + (size_t)NB * NH;

    const float4* wd4 = reinterpret_cast<const float4*>(g_wdst);
    float4 d0 = wd4[2 * l], d1 = wd4[2 * l + 1];

    auto compute_adst = [&](int b) -> float {
        const float4* o4 = reinterpret_cast<const float4*>(g_out + (size_t)b * NH);
        return warp_sum(dot4(o4[2 * l], d0) + dot4(o4[2 * l + 1], d1));
    };
    auto acc8 = [&](uint4 v, float wgt, float* a) {
        __half2 h; float2 f;
        *reinterpret_cast<unsigned*>(&h) = v.x; f = __half22float2(h);
        a[0] += wgt * f.x; a[1] += wgt * f.y;
        *reinterpret_cast<unsigned*>(&h) = v.y; f = __half22float2(h);
        a[2] += wgt * f.x; a[3] += wgt * f.y;
        *reinterpret_cast<unsigned*>(&h) = v.z; f = __half22float2(h);
        a[4] += wgt * f.x; a[5] += wgt * f.y;
        *reinterpret_cast<unsigned*>(&h) = v.w; f = __half22float2(h);
        a[6] += wgt * f.x; a[7] += wgt * f.y;
    };

    float a[8];
#pragma unroll
    for (int j = 0; j < 8; j++) a[j] = 0.f;
    float ds = 0.f;

    if (lo < hi) {
        int b0 = batch[lo], b1 = batch[hi - 1];
        if (b0 == b1) {
            float adst = compute_adst(b0);
            int i = lo;
            for (; i + 8 <= hi; i += 8) {
                const uint4* r = reinterpret_cast<const uint4*>(g_x16 + (size_t)i * NH);
                uint4 v0 = r[l],       v1 = r[32 + l],  v2 = r[64 + l],  v3 = r[96 + l];
                uint4 v4 = r[128 + l], v5 = r[160 + l], v6 = r[192 + l], v7 = r[224 + l];
                const float4* ap = reinterpret_cast<const float4*>(&g_asrc[i]);
                float4 ea = ap[0], eb = ap[1];
                float g[8] = {ea.x + adst, ea.y + adst, ea.z + adst, ea.w + adst,
                              eb.x + adst, eb.y + adst, eb.z + adst, eb.w + adst};
#pragma unroll
                for (int u = 0; u < 8; u++) {
                    float e = g[u];
                    e = e > 0.f ? e : 0.01f * e;
                    g[u] = __expf(e);
                    ds += g[u];
                }
                acc8(v0, g[0], a); acc8(v1, g[1], a); acc8(v2, g[2], a); acc8(v3, g[3], a);
                acc8(v4, g[4], a); acc8(v5, g[5], a); acc8(v6, g[6], a); acc8(v7, g[7], a);
            }
            for (; i < hi; i++) {
                float e = g_asrc[i] + adst;
                e = e > 0.f ? e : 0.01f * e;
                float wgt = __expf(e);
                ds += wgt;
                const uint4* r = reinterpret_cast<const uint4*>(g_x16 + (size_t)i * NH);
                acc8(r[l], wgt, a);
            }
            int slot = b0 - fg;
            if (slot < NSLOT) {
                flushC(&sacc[slot][0], l, a);
                if (l == 0) atomicAdd(&sds[slot], ds);
            } else {
                flushC(&g_sacc[(size_t)b0 * NH], l, a);
                if (l == 0) atomicAdd(&gdsum[b0], ds);
            }
        } else {
            int cur = b0;
            float adst = compute_adst(cur);
            for (int i = lo; i < hi; i++) {
                int bb = batch[i];
                if (bb != cur) {
                    int slot = cur - fg;
                    if (slot < NSLOT) {
                        flushC(&sacc[slot][0], l, a);
                        if (l == 0) atomicAdd(&sds[slot], ds);
                    } else {
                        flushC(&g_sacc[(size_t)cur * NH], l, a);
                        if (l == 0) atomicAdd(&gdsum[cur], ds);
                    }
#pragma unroll
                    for (int j = 0; j < 8; j++) a[j] = 0.f;
                    ds = 0.f;
                    cur = bb;
                    adst = compute_adst(cur);
                }
                float e = g_asrc[i] + adst;
                e = e > 0.f ? e : 0.01f * e;
                float wgt = __expf(e);
                ds += wgt;
                const uint4* r = reinterpret_cast<const uint4*>(g_x16 + (size_t)i * NH);
                acc8(r[l], wgt, a);
            }
            int slot = cur - fg;
            if (slot < NSLOT) {
                flushC(&sacc[slot][0], l, a);
                if (l == 0) atomicAdd(&sds[slot], ds);
            } else {
                flushC(&g_sacc[(size_t)cur * NH], l, a);
                if (l == 0) atomicAdd(&gdsum[cur], ds);
            }
        }
    }
    __syncthreads();
    int last = min(base + CH, n) - 1;
    int nspan = min(batch[last] - fg + 1, NSLOT);
    for (int s = 0; s < nspan; s++)
        atomicAdd(&g_sacc[(size_t)(fg + s) * NH + tid], sacc[s][tid]);
    if (tid < nspan) atomicAdd(&gdsum[fg + tid], sds[tid]);
}

// ------ 3xTF32 GEMM, NT, pre-split B, R14 layout + dynamic-smem double buffer ----
// Per buffer: AsH, AsL, BsH, BsL each [64][36] (padded, conflict-free). One sync/iter.
template <int ACT, int SCALE>
__device__ __forceinline__ void gemm_nt(unsigned* dsm,
                                        const float* __restrict__ A,
                                        const unsigned* __restrict__ BH,
                                        const unsigned* __restrict__ BL,
                                        const float* __restrict__ bias, float* __restrict__ C,
                                        int N, int bm, int bn) {
    const int K = 256;
    int tid = threadIdx.x;
    int lane = tid & 31, wp = tid >> 5;       // 8 warps
    int wm = wp >> 1, wn = wp & 1;            // 4 x 2
    int g = lane >> 2, t = lane & 3;
    float acc[4][4];
#pragma unroll
    for (int j = 0; j < 4; j++)
#pragma unroll
        for (int r = 0; r < 4; r++) acc[j][r] = 0.f;

    // prefetch registers (double buffer in RF)
    float4 pva[2];
    uint4  pvh[2], pvl[2];
    int m0 = tid >> 3, kq0 = tid & 7;              // r = 0
    int m1 = (tid + 256) >> 3, kq1 = tid & 7;      // r = 1
    size_t aoff0 = (size_t)(bm + m0) * K + kq0 * 4;
    size_t aoff1 = (size_t)(bm + m1) * K + kq1 * 4;
    size_t boff0 = (size_t)(bn + m0) * K + kq0 * 4;
    size_t boff1 = (size_t)(bn + m1) * K + kq1 * 4;

    auto fetch = [&](int k0) {
        pva[0] = *reinterpret_cast<const float4*>(&A[aoff0 + k0]);
        pva[1] = *reinterpret_cast<const float4*>(&A[aoff1 + k0]);
        pvh[0] = *reinterpret_cast<const uint4*>(&BH[boff0 + k0]);
        pvh[1] = *reinterpret_cast<const uint4*>(&BH[boff1 + k0]);
        pvl[0] = *reinterpret_cast<const uint4*>(&BL[boff0 + k0]);
        pvl[1] = *reinterpret_cast<const uint4*>(&BL[boff1 + k0]);
    };
    auto stage = [&](int buf) {
        unsigned (*AsH)[36] = reinterpret_cast<unsigned (*)[36]>(dsm + buf * GBUF);
        unsigned (*AsL)[36] = reinterpret_cast<unsigned (*)[36]>(dsm + buf * GBUF + 64 * 36);
        unsigned (*BsH)[36] = reinterpret_cast<unsigned (*)[36]>(dsm + buf * GBUF + 2 * 64 * 36);
        unsigned (*BsL)[36] = reinterpret_cast<unsigned (*)[36]>(dsm + buf * GBUF + 3 * 64 * 36);
#pragma unroll
        for (int r = 0; r < 2; r++) {
            int m = r ? m1 : m0;
            int kq = r ? kq1 : kq0;
            float4 va = pva[r];
            split_tf32(va.x, AsH[m][kq * 4 + 0], AsL[m][kq * 4 + 0]);
            split_tf32(va.y, AsH[m][kq * 4 + 1], AsL[m][kq * 4 + 1]);
            split_tf32(va.z, AsH[m][kq * 4 + 2], AsL[m][kq * 4 + 2]);
            split_tf32(va.w, AsH[m][kq * 4 + 3], AsL[m][kq * 4 + 3]);
            uint4 vh = pvh[r];
            BsH[m][kq * 4 + 0] = vh.x; BsH[m][kq * 4 + 1] = vh.y;
            BsH[m][kq * 4 + 2] = vh.z; BsH[m][kq * 4 + 3] = vh.w;
            uint4 vl = pvl[r];
            BsL[m][kq * 4 + 0] = vl.x; BsL[m][kq * 4 + 1] = vl.y;
            BsL[m][kq * 4 + 2] = vl.z; BsL[m][kq * 4 + 3] = vl.w;
        }
    };

    fetch(0);
    stage(0);
    __syncthreads();
    for (int it = 0; it < 8; it++) {
        int cur = it & 1;
        if (it < 7) fetch((it + 1) * 32);   // global loads fly during compute below
        unsigned (*AsH)[36] = reinterpret_cast<unsigned (*)[36]>(dsm + cur * GBUF);
        unsigned (*AsL)[36] = reinterpret_cast<unsigned (*)[36]>(dsm + cur * GBUF + 64 * 36);
        unsigned (*BsH)[36] = reinterpret_cast<unsigned (*)[36]>(dsm + cur * GBUF + 2 * 64 * 36);
        unsigned (*BsL)[36] = reinterpret_cast<unsigned (*)[36]>(dsm + cur * GBUF + 3 * 64 * 36);
#pragma unroll
        for (int ks = 0; ks < 4; ks++) {
            int k8 = ks * 8;
            unsigned afH[4], afL[4], bfH[4][2], bfL[4][2];
            int r0 = wm * 16 + g;
            afH[0] = AsH[r0][k8 + t];      afL[0] = AsL[r0][k8 + t];
            afH[1] = AsH[r0 + 8][k8 + t];  afL[1] = AsL[r0 + 8][k8 + t];
            afH[2] = AsH[r0][k8 + t + 4];  afL[2] = AsL[r0][k8 + t + 4];
            afH[3] = AsH[r0 + 8][k8 + t + 4]; afL[3] = AsL[r0 + 8][k8 + t + 4];
#pragma unroll
            for (int tj = 0; tj < 4; tj++) {
                int nr = wn * 32 + tj * 8 + g;
                bfH[tj][0] = BsH[nr][k8 + t];     bfL[tj][0] = BsL[nr][k8 + t];
                bfH[tj][1] = BsH[nr][k8 + t + 4]; bfL[tj][1] = BsL[nr][k8 + t + 4];
            }
#pragma unroll
            for (int tj = 0; tj < 4; tj++) {
                mma_tf32(acc[tj], afH, bfH[tj]);
                mma_tf32(acc[tj], afH, bfL[tj]);
                mma_tf32(acc[tj], afL, bfH[tj]);
            }
        }
        if (it < 7) stage(1 - cur);         // writes the other buffer; safe pre-sync
        __syncthreads();
    }
    const float* dsum = g_sacc + (size_t)NB * NH;
    {
        int r0 = bm + wm * 16 + g;
        float invl = 1.f, invh = 1.f;
        if (SCALE) {
            float dv0 = dsum[r0];
            float dv1 = dsum[r0 + 8];
            invl = dv0 > 0.f ? 1.f / dv0 : 0.f;
            invh = dv1 > 0.f ? 1.f / dv1 : 0.f;
        }
#pragma unroll
        for (int tj = 0; tj < 4; tj++) {
            int col = bn + wn * 32 + tj * 8 + 2 * t;
            float b0 = bias[col], b1 = bias[col + 1];
            float c0 = acc[tj][0] * invl + b0;
            float c1 = acc[tj][1] * invl + b1;
            float c2 = acc[tj][2] * invh + b0;
            float c3 = acc[tj][3] * invh + b1;
            if (ACT) {
                c0 = c0 > 0.f ? c0 : expm1f(c0);
                c1 = c1 > 0.f ? c1 : expm1f(c1);
                c2 = c2 > 0.f ? c2 : expm1f(c2);
                c3 = c3 > 0.f ? c3 : expm1f(c3);
            }
            *reinterpret_cast<float2*>(&C[(size_t)r0 * N + col]) = make_float2(c0, c1);
            *reinterpret_cast<float2*>(&C[(size_t)(r0 + 8) * N + col]) = make_float2(c2, c3);
        }
    }
}

// h = elu((sacc/dsum) @ W + bias_gat) [64 blocks] + gh = out @ W_hh^T + b_hh [192]
__global__ void __launch_bounds__(256)
gemm_h_gh_kernel(const float* __restrict__ bias_gat, const float* __restrict__ b_hh) {
    extern __shared__ __align__(16) unsigned dsm[];
    int bid = blockIdx.x;
    if (bid < 64)
        gemm_nt<1, 1>(dsm, g_sacc, g_WTH, g_WTL, bias_gat, g_h, NH,
                      (bid >> 2) * 64, (bid & 3) * 64);
    else {
        int b2 = bid - 64;
        gemm_nt<0, 0>(dsm, g_out, g_WhhH, g_WhhL, b_hh, g_gh, G3H,
                      (b2 / 12) * 64, (b2 % 12) * 64);
    }
}

__global__ void __launch_bounds__(256)
gemm_gi_kernel(const float* __restrict__ b_ih) {
    extern __shared__ __align__(16) unsigned dsm[];
    gemm_nt<0, 0>(dsm, g_h, g_WihH, g_WihL, b_ih, g_gi, G3H,
                  (blockIdx.x / 12) * 64, (blockIdx.x % 12) * 64);
}

__global__ void __launch_bounds__(256)
gemm_final_kernel(const float* __restrict__ b_lin, float* __restrict__ out) {
    extern __shared__ __align__(16) unsigned dsm[];
    gemm_nt<0, 0>(dsm, g_out, g_WlinTH, g_WlinTL, b_lin, out, NOUT,
                  (blockIdx.x >> 1) * 64, (blockIdx.x & 1) * 64);
}

// ------------- GRU elementwise update (in place) + zero sacc for next t ----------
__global__ void gru_kernel() {
    int idx = blockIdx.x * blockDim.x + threadIdx.x;   // 256 blocks x 256 = 65536
    int b = idx >> 6, h4 = idx & 63;
    const float4* gi4 = reinterpret_cast<const float4*>(g_gi) + (size_t)b * (G3H / 4);
    const float4* gh4 = reinterpret_cast<const float4*>(g_gh) + (size_t)b * (G3H / 4);
    float4 gir = gi4[h4], giz = gi4[64 + h4], gin = gi4[128 + h4];
    float4 ghr = gh4[h4], ghz = gh4[64 + h4], ghn = gh4[128 + h4];
    float4* out4 = reinterpret_cast<float4*>(g_out) + idx;
    float4 o = *out4;
    float4 res;
    {
        float r = sigmoidf_(gir.x + ghr.x), z = sigmoidf_(giz.x + ghz.x);
        float nn = tanhf(gin.x + r * ghn.x);
        float v = (1.f - z) * nn + z * o.x; res.x = v * sigmoidf_(v);
    }
    {
        float r = sigmoidf_(gir.y + ghr.y), z = sigmoidf_(giz.y + ghz.y);
        float nn = tanhf(gin.y + r * ghn.y);
        float v = (1.f - z) * nn + z * o.y; res.y = v * sigmoidf_(v);
    }
    {
        float r = sigmoidf_(gir.z + ghr.z), z = sigmoidf_(giz.z + ghz.z);
        float nn = tanhf(gin.z + r * ghn.z);
        float v = (1.f - z) * nn + z * o.z; res.z = v * sigmoidf_(v);
    }
    {
        float r = sigmoidf_(gir.w + ghr.w), z = sigmoidf_(giz.w + ghz.w);
        float nn = tanhf(gin.w + r * ghn.w);
        float v = (1.f - z) * nn + z * o.w; res.w = v * sigmoidf_(v);
    }
    *out4 = res;
    float4 zz = make_float4(0.f, 0.f, 0.f, 0.f);
    float4* s4 = reinterpret_cast<float4*>(g_sacc);
    for (int i = idx; i < (NB * NH + NB) / 4; i += 65536) s4[i] = zz;
}

// ---------------- launch (single stream) ----------------
extern "C" void kernel_launch(void* const* d_in, const int* in_sizes, int n_in,
                              void* d_out, int out_size) {
    const float* x        = (const float*)d_in[0];
    const int*   batch    = (const int*)d_in[1];
    const float* W        = (const float*)d_in[2];
    const float* att_src  = (const float*)d_in[3];
    const float* att_dst  = (const float*)d_in[4];
    const float* bias_gat = (const float*)d_in[5];
    const float* W_ih     = (const float*)d_in[6];
    const float* W_hh     = (const float*)d_in[7];
    const float* b_ih     = (const float*)d_in[8];
    const float* b_hh     = (const float*)d_in[9];
    const float* W_lin    = (const float*)d_in[10];
    const float* b_lin    = (const float*)d_in[11];
    float*       out      = (float*)d_out;

    const int n = in_sizes[1];
    const int nch = (n + CH - 1) / CH;
    const float4* x4 = reinterpret_cast<const float4*>(x);

    // raise dynamic smem limit for the GEMM kernels (host-side attr, capture-safe)
    cudaFuncSetAttribute(gemm_h_gh_kernel,
                         cudaFuncAttributeMaxDynamicSharedMemorySize, GEMM_SMEM_BYTES);
    cudaFuncSetAttribute(gemm_gi_kernel,
                         cudaFuncAttributeMaxDynamicSharedMemorySize, GEMM_SMEM_BYTES);
    cudaFuncSetAttribute(gemm_final_kernel,
                         cudaFuncAttributeMaxDynamicSharedMemorySize, GEMM_SMEM_BYTES);

    prep_kernel<<<704, 256>>>(W, att_src, att_dst, W_lin, W_ih, W_hh);
    phaseA_kernel<<<nch, 256>>>(x4, batch, n);

    for (int t = 0; t < 2; t++) {
        attnpool_kernel<<<nch, 256>>>(batch, n);
        gemm_h_gh_kernel<<<256, 256, GEMM_SMEM_BYTES>>>(bias_gat, b_hh);
        gemm_gi_kernel<<<192, 256, GEMM_SMEM_BYTES>>>(b_ih);
        gru_kernel<<<256, 256>>>();
    }

    gemm_final_kernel<<<32, 256, GEMM_SMEM_BYTES>>>(b_lin, out);
}

// round 17
// speedup vs baseline: 1.1419x; 1.0257x over previous
#include <cuda_runtime.h>
#include <cuda_fp16.h>
#include <math.h>

#define NNODES 200000
#define NB     1024
#define NH     256
#define NH4    64
#define G3H    768
#define NOUT   128
#define CH     256      // nodes per pool chunk
#define NSLOT  8

#define SMEM2 (2 * 3 * 64 * 36 * 4)   // 2 buffers x (AsH,AsL,BsH)      = 55296 B
#define SMEM3 (2 * 4 * 64 * 36 * 4)   // 2 buffers x (AsH,AsL,BsH,BsL)  = 73728 B

// ---------------- scratch ----------------
__device__ __align__(16) __half g_x16[(size_t)NNODES * NH];   // fp16 copy of x
__device__ __align__(16) float g_wsrc[NH];
__device__ __align__(16) float g_wdst[NH];
__device__ __align__(16) float g_asrc[NNODES];
__device__ __align__(16) float g_out[NB * NH];
__device__ __align__(16) float g_sacc[NB * NH + NB];   // last NB floats = dsum
__device__ __align__(16) float g_h[NB * NH];
__device__ __align__(16) float g_gi[NB * G3H];
__device__ __align__(16) float g_gh[NB * G3H];
// pre-split tf32 weights (hi/lo)
__device__ __align__(16) unsigned g_WTH[NH * NH],      g_WTL[NH * NH];
__device__ __align__(16) unsigned g_WlinTH[NOUT * NH], g_WlinTL[NOUT * NH];
__device__ __align__(16) unsigned g_WihH[G3H * NH],    g_WihL[G3H * NH];
__device__ __align__(16) unsigned g_WhhH[G3H * NH],    g_WhhL[G3H * NH];

// ---------------- helpers ----------------
__device__ __forceinline__ float warp_sum(float v) {
#pragma unroll
    for (int off = 16; off; off >>= 1) v += __shfl_xor_sync(0xffffffffu, v, off);
    return v;
}
__device__ __forceinline__ float sigmoidf_(float x) { return 1.0f / (1.0f + expf(-x)); }
__device__ __forceinline__ float dot4(float4 a, float4 b) {
    return a.x * b.x + a.y * b.y + a.z * b.z + a.w * b.w;
}
__device__ __forceinline__ unsigned to_tf32(float x) {
    unsigned r;
    asm("cvt.rna.tf32.f32 %0, %1;" : "=r"(r) : "f"(x));
    return r;
}
__device__ __forceinline__ void split_tf32(float v, unsigned& hi, unsigned& lo) {
    hi = to_tf32(v);
    lo = to_tf32(v - __uint_as_float(hi));
}
__device__ __forceinline__ void mma_tf32(float* c, const unsigned* a, const unsigned* b) {
    asm volatile(
        "mma.sync.aligned.m16n8k8.row.col.f32.tf32.tf32.f32 "
        "{%0,%1,%2,%3}, {%4,%5,%6,%7}, {%8,%9}, {%0,%1,%2,%3};"
        : "+f"(c[0]), "+f"(c[1]), "+f"(c[2]), "+f"(c[3])
        : "r"(a[0]), "r"(a[1]), "r"(a[2]), "r"(a[3]), "r"(b[0]), "r"(b[1]));
}

// ------ prep: watt[0,64) + zero[64,192) + transpose-split[192,320) + split[320,704)
__global__ void prep_kernel(const float* __restrict__ W,
                            const float* __restrict__ att_src,
                            const float* __restrict__ att_dst,
                            const float* __restrict__ Wlin,
                            const float* __restrict__ W_ih,
                            const float* __restrict__ W_hh) {
    int bid = blockIdx.x;
    int tid = threadIdx.x;
    if (bid < 64) {
        int g = (bid * 256 + tid) >> 5;
        int l = tid & 31;
        int row = g & (NH - 1);
        bool isdst = g >= NH;
        const float4* Wr = reinterpret_cast<const float4*>(W + (size_t)row * NH);
        const float4* av = reinterpret_cast<const float4*>(isdst ? att_dst : att_src);
        float p = dot4(Wr[l], av[l]) + dot4(Wr[32 + l], av[32 + l]);
        p = warp_sum(p);
        if (l == 0) (isdst ? g_wdst : g_wsrc)[row] = p;
    } else if (bid < 192) {
        int idx = (bid - 64) * 256 + tid;
        int stride = 128 * 256;
        float4 z = make_float4(0.f, 0.f, 0.f, 0.f);
        float4* o = reinterpret_cast<float4*>(g_out);
        for (int i = idx; i < NB * NH / 4; i += stride) o[i] = z;
        float4* s = reinterpret_cast<float4*>(g_sacc);
        for (int i = idx; i < (NB * NH + NB) / 4; i += stride) s[i] = z;
    } else if (bid < 320) {
        // transpose + split: W -> WTH/WTL, Wlin -> WlinTH/WlinTL
        __shared__ float tile[32][33];
        int b = bid - 192;
        int z = b >> 6;
        int bx = (b & 7) * 32, by = ((b >> 3) & 7) * 32;
        const float* src = z ? Wlin : W;
        unsigned* dH = z ? g_WlinTH : g_WTH;
        unsigned* dL = z ? g_WlinTL : g_WTL;
        int C = z ? NOUT : NH;
        if (bx >= C) return;
        int tx = tid & 31, ty = tid >> 5;
#pragma unroll
        for (int j = 0; j < 32; j += 8)
            tile[ty + j][tx] = src[(size_t)(by + ty + j) * C + bx + tx];
        __syncthreads();
#pragma unroll
        for (int j = 0; j < 32; j += 8) {
            float v = tile[tx][ty + j];
            unsigned hv, lv;
            split_tf32(v, hv, lv);
            dH[(size_t)(bx + ty + j) * NH + by + tx] = hv;
            dL[(size_t)(bx + ty + j) * NH + by + tx] = lv;
        }
    } else {
        // elementwise split of W_ih / W_hh (row-major [G3H, NH])
        int idx = (bid - 320) * 256 + tid;      // float4 index, 2*49152 total
        const float4* src;
        unsigned *dH, *dL;
        if (idx < G3H * NH / 4) {
            src = reinterpret_cast<const float4*>(W_ih);
            dH = g_WihH; dL = g_WihL;
        } else {
            idx -= G3H * NH / 4;
            src = reinterpret_cast<const float4*>(W_hh);
            dH = g_WhhH; dL = g_WhhL;
        }
        float4 v = src[idx];
        uint4 hv, lv;
        split_tf32(v.x, hv.x, lv.x);
        split_tf32(v.y, hv.y, lv.y);
        split_tf32(v.z, hv.z, lv.z);
        split_tf32(v.w, hv.w, lv.w);
        *reinterpret_cast<uint4*>(&dH[(size_t)idx * 4]) = hv;
        *reinterpret_cast<uint4*>(&dL[(size_t)idx * 4]) = lv;
    }
}

// flush helpers (feature-contiguous, 8 per lane)
__device__ __forceinline__ void flush8(float* dst, int l, float4 a0, float4 a1) {
    float* p = dst + l * 8;
    atomicAdd(p + 0, a0.x); atomicAdd(p + 1, a0.y);
    atomicAdd(p + 2, a0.z); atomicAdd(p + 3, a0.w);
    atomicAdd(p + 4, a1.x); atomicAdd(p + 5, a1.y);
    atomicAdd(p + 6, a1.z); atomicAdd(p + 7, a1.w);
}
__device__ __forceinline__ void flushC(float* dst, int l, const float* a) {
    float* p = dst + l * 8;
#pragma unroll
    for (int j = 0; j < 8; j++) atomicAdd(p + j, a[j]);
}

// ---------------- phase A: sum-pool + asrc + fp16 conversion ----------------
// Lane l owns features 8l..8l+7 (paired float4 loads, single STG.128 conv store).
__global__ void __launch_bounds__(256, 6)
phaseA_kernel(const float4* __restrict__ x4, const int* __restrict__ batch, int n) {
    int base = blockIdx.x * CH;
    int tid = threadIdx.x, w = tid >> 5, l = tid & 31;
    __shared__ float sacc[NSLOT][NH];
    for (int i = tid; i < NSLOT * NH; i += 256) (&sacc[0][0])[i] = 0.f;
    __syncthreads();
    int fg = batch[base];
    int lo = base + w * 32;
    int hi = min(base + (w + 1) * 32, n);

    const float4* wa = reinterpret_cast<const float4*>(g_wsrc);
    float4 w0 = wa[2 * l], w1 = wa[2 * l + 1];
    float4 a0 = make_float4(0.f, 0.f, 0.f, 0.f);
    float4 a1 = make_float4(0.f, 0.f, 0.f, 0.f);

    auto conv = [&](int i, float4 u0, float4 u1) {
        __half2 h0 = __floats2half2_rn(u0.x, u0.y), h1 = __floats2half2_rn(u0.z, u0.w);
        __half2 h2 = __floats2half2_rn(u1.x, u1.y), h3 = __floats2half2_rn(u1.z, u1.w);
        uint4 p;
        p.x = *reinterpret_cast<unsigned*>(&h0); p.y = *reinterpret_cast<unsigned*>(&h1);
        p.z = *reinterpret_cast<unsigned*>(&h2); p.w = *reinterpret_cast<unsigned*>(&h3);
        *reinterpret_cast<uint4*>(g_x16 + (size_t)i * NH + l * 8) = p;
    };
    auto add8 = [&](float4 u0, float4 u1) {
        a0.x += u0.x; a0.y += u0.y; a0.z += u0.z; a0.w += u0.w;
        a1.x += u1.x; a1.y += u1.y; a1.z += u1.z; a1.w += u1.w;
    };

    if (lo < hi) {
        int b0 = batch[lo], b1 = batch[hi - 1];
        if (b0 == b1) {
            int i = lo;
            for (; i + 4 <= hi; i += 4) {
                const float4* r = x4 + (size_t)i * NH4;
                float4 u0 = r[2 * l],       u1 = r[2 * l + 1];
                float4 v0 = r[64 + 2 * l],  v1 = r[64 + 2 * l + 1];
                float4 s0 = r[128 + 2 * l], s1 = r[128 + 2 * l + 1];
                float4 t0 = r[192 + 2 * l], t1 = r[192 + 2 * l + 1];
                conv(i, u0, u1); conv(i + 1, v0, v1);
                conv(i + 2, s0, s1); conv(i + 3, t0, t1);
                add8(u0, u1); add8(v0, v1); add8(s0, s1); add8(t0, t1);
                float p0 = dot4(u0, w0) + dot4(u1, w1);
                float p1 = dot4(v0, w0) + dot4(v1, w1);
                float p2 = dot4(s0, w0) + dot4(s1, w1);
                float p3 = dot4(t0, w0) + dot4(t1, w1);
#pragma unroll
                for (int off = 16; off; off >>= 1) {
                    p0 += __shfl_xor_sync(0xffffffffu, p0, off);
                    p1 += __shfl_xor_sync(0xffffffffu, p1, off);
                    p2 += __shfl_xor_sync(0xffffffffu, p2, off);
                    p3 += __shfl_xor_sync(0xffffffffu, p3, off);
                }
                if (l == 0)
                    *reinterpret_cast<float4*>(&g_asrc[i]) = make_float4(p0, p1, p2, p3);
            }
            for (; i < hi; i++) {
                const float4* r = x4 + (size_t)i * NH4;
                float4 u0 = r[2 * l], u1 = r[2 * l + 1];
                conv(i, u0, u1);
                add8(u0, u1);
                float p = warp_sum(dot4(u0, w0) + dot4(u1, w1));
                if (l == 0) g_asrc[i] = p;
            }
            int slot = b0 - fg;
            flush8(slot < NSLOT ? &sacc[slot][0] : &g_out[(size_t)b0 * NH], l, a0, a1);
        } else {
            int cur = b0;
            for (int i = lo; i < hi; i++) {
                int bb = batch[i];
                if (bb != cur) {
                    int slot = cur - fg;
                    flush8(slot < NSLOT ? &sacc[slot][0] : &g_out[(size_t)cur * NH], l, a0, a1);
                    a0 = make_float4(0.f, 0.f, 0.f, 0.f);
                    a1 = make_float4(0.f, 0.f, 0.f, 0.f);
                    cur = bb;
                }
                const float4* r = x4 + (size_t)i * NH4;
                float4 u0 = r[2 * l], u1 = r[2 * l + 1];
                conv(i, u0, u1);
                add8(u0, u1);
                float p = warp_sum(dot4(u0, w0) + dot4(u1, w1));
                if (l == 0) g_asrc[i] = p;
            }
            int slot = cur - fg;
            flush8(slot < NSLOT ? &sacc[slot][0] : &g_out[(size_t)cur * NH], l, a0, a1);
        }
    }
    __syncthreads();
    int last = min(base + CH, n) - 1;
    int nspan = min(batch[last] - fg + 1, NSLOT);
    for (int s = 0; s < nspan; s++)
        atomicAdd(&g_out[(size_t)(fg + s) * NH + tid], sacc[s][tid]);
}

// ---------------- attention pool (fp16 x, fused adst, unnormalized + dsum) -------
__global__ void __launch_bounds__(256, 6)
attnpool_kernel(const int* __restrict__ batch, int n) {
    int base = blockIdx.x * CH;
    int tid = threadIdx.x, w = tid >> 5, l = tid & 31;
    __shared__ float sacc[NSLOT][NH];
    __shared__ float sds[NSLOT];
    for (int i = tid; i < NSLOT * NH; i += 256) (&sacc[0][0])[i] = 0.f;
    if (tid < NSLOT) sds[tid] = 0.f;
    __syncthreads();
    int fg = batch[base];
    int lo = base + w * 32;
    int hi = min(base + (w + 1) * 32, n);
    float* gdsum = g_sacc + (size_t)NB * NH;

    const float4* wd4 = reinterpret_cast<const float4*>(g_wdst);
    float4 d0 = wd4[2 * l], d1 = wd4[2 * l + 1];

    auto compute_adst = [&](int b) -> float {
        const float4* o4 = reinterpret_cast<const float4*>(g_out + (size_t)b * NH);
        return warp_sum(dot4(o4[2 * l], d0) + dot4(o4[2 * l + 1], d1));
    };
    auto acc8 = [&](uint4 v, float wgt, float* a) {
        __half2 h; float2 f;
        *reinterpret_cast<unsigned*>(&h) = v.x; f = __half22float2(h);
        a[0] += wgt * f.x; a[1] += wgt * f.y;
        *reinterpret_cast<unsigned*>(&h) = v.y; f = __half22float2(h);
        a[2] += wgt * f.x; a[3] += wgt * f.y;
        *reinterpret_cast<unsigned*>(&h) = v.z; f = __half22float2(h);
        a[4] += wgt * f.x; a[5] += wgt * f.y;
        *reinterpret_cast<unsigned*>(&h) = v.w; f = __half22float2(h);
        a[6] += wgt * f.x; a[7] += wgt * f.y;
    };

    float a[8];
#pragma unroll
    for (int j = 0; j < 8; j++) a[j] = 0.f;
    float ds = 0.f;

    if (lo < hi) {
        int b0 = batch[lo], b1 = batch[hi - 1];
        if (b0 == b1) {
            float adst = compute_adst(b0);
            int i = lo;
            for (; i + 8 <= hi; i += 8) {
                const uint4* r = reinterpret_cast<const uint4*>(g_x16 + (size_t)i * NH);
                uint4 v0 = r[l],       v1 = r[32 + l],  v2 = r[64 + l],  v3 = r[96 + l];
                uint4 v4 = r[128 + l], v5 = r[160 + l], v6 = r[192 + l], v7 = r[224 + l];
                const float4* ap = reinterpret_cast<const float4*>(&g_asrc[i]);
                float4 ea = ap[0], eb = ap[1];
                float g[8] = {ea.x + adst, ea.y + adst, ea.z + adst, ea.w + adst,
                              eb.x + adst, eb.y + adst, eb.z + adst, eb.w + adst};
#pragma unroll
                for (int u = 0; u < 8; u++) {
                    float e = g[u];
                    e = e > 0.f ? e : 0.01f * e;
                    g[u] = __expf(e);
                    ds += g[u];
                }
                acc8(v0, g[0], a); acc8(v1, g[1], a); acc8(v2, g[2], a); acc8(v3, g[3], a);
                acc8(v4, g[4], a); acc8(v5, g[5], a); acc8(v6, g[6], a); acc8(v7, g[7], a);
            }
            for (; i < hi; i++) {
                float e = g_asrc[i] + adst;
                e = e > 0.f ? e : 0.01f * e;
                float wgt = __expf(e);
                ds += wgt;
                const uint4* r = reinterpret_cast<const uint4*>(g_x16 + (size_t)i * NH);
                acc8(r[l], wgt, a);
            }
            int slot = b0 - fg;
            if (slot < NSLOT) {
                flushC(&sacc[slot][0], l, a);
                if (l == 0) atomicAdd(&sds[slot], ds);
            } else {
                flushC(&g_sacc[(size_t)b0 * NH], l, a);
                if (l == 0) atomicAdd(&gdsum[b0], ds);
            }
        } else {
            int cur = b0;
            float adst = compute_adst(cur);
            for (int i = lo; i < hi; i++) {
                int bb = batch[i];
                if (bb != cur) {
                    int slot = cur - fg;
                    if (slot < NSLOT) {
                        flushC(&sacc[slot][0], l, a);
                        if (l == 0) atomicAdd(&sds[slot], ds);
                    } else {
                        flushC(&g_sacc[(size_t)cur * NH], l, a);
                        if (l == 0) atomicAdd(&gdsum[cur], ds);
                    }
#pragma unroll
                    for (int j = 0; j < 8; j++) a[j] = 0.f;
                    ds = 0.f;
                    cur = bb;
                    adst = compute_adst(cur);
                }
                float e = g_asrc[i] + adst;
                e = e > 0.f ? e : 0.01f * e;
                float wgt = __expf(e);
                ds += wgt;
                const uint4* r = reinterpret_cast<const uint4*>(g_x16 + (size_t)i * NH);
                acc8(r[l], wgt, a);
            }
            int slot = cur - fg;
            if (slot < NSLOT) {
                flushC(&sacc[slot][0], l, a);
                if (l == 0) atomicAdd(&sds[slot], ds);
            } else {
                flushC(&g_sacc[(size_t)cur * NH], l, a);
                if (l == 0) atomicAdd(&gdsum[cur], ds);
            }
        }
    }
    __syncthreads();
    int last = min(base + CH, n) - 1;
    int nspan = min(batch[last] - fg + 1, NSLOT);
    for (int s = 0; s < nspan; s++)
        atomicAdd(&g_sacc[(size_t)(fg + s) * NH + tid], sacc[s][tid]);
    if (tid < nspan) atomicAdd(&gdsum[fg + tid], sds[tid]);
}

// ------ tf32 GEMM, NT, pre-split, double-buffered. TERMS=2: aH*bH + aL*bH (B tf32).
// TERMS=3 adds aH*bL (full-precision path, used for the final GEMM).
template <int TERMS, int ACT, int SCALE>
__device__ __forceinline__ void gemm_nt(unsigned* dsm,
                                        const float* __restrict__ A,
                                        const unsigned* __restrict__ BH,
                                        const unsigned* __restrict__ BL,
                                        const float* __restrict__ bias, float* __restrict__ C,
                                        int N, int bm, int bn) {
    const int K = 256;
    const int GB = (TERMS == 3 ? 4 : 3) * 64 * 36;    // words per buffer
    int tid = threadIdx.x;
    int lane = tid & 31, wp = tid >> 5;       // 8 warps
    int wm = wp >> 1, wn = wp & 1;            // 4 x 2
    int g = lane >> 2, t = lane & 3;
    float acc[4][4];
#pragma unroll
    for (int j = 0; j < 4; j++)
#pragma unroll
        for (int r = 0; r < 4; r++) acc[j][r] = 0.f;

    // prefetch registers
    float4 pva[2];
    uint4  pvh[2], pvl[2];
    int m0 = tid >> 3, kq0 = tid & 7;
    int m1 = (tid + 256) >> 3, kq1 = tid & 7;
    size_t aoff0 = (size_t)(bm + m0) * K + kq0 * 4;
    size_t aoff1 = (size_t)(bm + m1) * K + kq1 * 4;
    size_t boff0 = (size_t)(bn + m0) * K + kq0 * 4;
    size_t boff1 = (size_t)(bn + m1) * K + kq1 * 4;

    auto fetch = [&](int k0) {
        pva[0] = *reinterpret_cast<const float4*>(&A[aoff0 + k0]);
        pva[1] = *reinterpret_cast<const float4*>(&A[aoff1 + k0]);
        pvh[0] = *reinterpret_cast<const uint4*>(&BH[boff0 + k0]);
        pvh[1] = *reinterpret_cast<const uint4*>(&BH[boff1 + k0]);
        if (TERMS == 3) {
            pvl[0] = *reinterpret_cast<const uint4*>(&BL[boff0 + k0]);
            pvl[1] = *reinterpret_cast<const uint4*>(&BL[boff1 + k0]);
        }
    };
    auto stage = [&](int buf) {
        unsigned (*AsH)[36] = reinterpret_cast<unsigned (*)[36]>(dsm + buf * GB);
        unsigned (*AsL)[36] = reinterpret_cast<unsigned (*)[36]>(dsm + buf * GB + 64 * 36);
        unsigned (*BsH)[36] = reinterpret_cast<unsigned (*)[36]>(dsm + buf * GB + 2 * 64 * 36);
        unsigned (*BsL)[36] = reinterpret_cast<unsigned (*)[36]>(dsm + buf * GB + 3 * 64 * 36);
#pragma unroll
        for (int r = 0; r < 2; r++) {
            int m = r ? m1 : m0;
            int kq = r ? kq1 : kq0;
            float4 va = pva[r];
            split_tf32(va.x, AsH[m][kq * 4 + 0], AsL[m][kq * 4 + 0]);
            split_tf32(va.y, AsH[m][kq * 4 + 1], AsL[m][kq * 4 + 1]);
            split_tf32(va.z, AsH[m][kq * 4 + 2], AsL[m][kq * 4 + 2]);
            split_tf32(va.w, AsH[m][kq * 4 + 3], AsL[m][kq * 4 + 3]);
            uint4 vh = pvh[r];
            BsH[m][kq * 4 + 0] = vh.x; BsH[m][kq * 4 + 1] = vh.y;
            BsH[m][kq * 4 + 2] = vh.z; BsH[m][kq * 4 + 3] = vh.w;
            if (TERMS == 3) {
                uint4 vl = pvl[r];
                BsL[m][kq * 4 + 0] = vl.x; BsL[m][kq * 4 + 1] = vl.y;
                BsL[m][kq * 4 + 2] = vl.z; BsL[m][kq * 4 + 3] = vl.w;
            }
        }
    };

    fetch(0);
    stage(0);
    __syncthreads();
    for (int it = 0; it < 8; it++) {
        int cur = it & 1;
        if (it < 7) fetch((it + 1) * 32);
        unsigned (*AsH)[36] = reinterpret_cast<unsigned (*)[36]>(dsm + cur * GB);
        unsigned (*AsL)[36] = reinterpret_cast<unsigned (*)[36]>(dsm + cur * GB + 64 * 36);
        unsigned (*BsH)[36] = reinterpret_cast<unsigned (*)[36]>(dsm + cur * GB + 2 * 64 * 36);
        unsigned (*BsL)[36] = reinterpret_cast<unsigned (*)[36]>(dsm + cur * GB + 3 * 64 * 36);
#pragma unroll
        for (int ks = 0; ks < 4; ks++) {
            int k8 = ks * 8;
            unsigned afH[4], afL[4], bfH[4][2], bfL[4][2];
            int r0 = wm * 16 + g;
            afH[0] = AsH[r0][k8 + t];      afL[0] = AsL[r0][k8 + t];
            afH[1] = AsH[r0 + 8][k8 + t];  afL[1] = AsL[r0 + 8][k8 + t];
            afH[2] = AsH[r0][k8 + t + 4];  afL[2] = AsL[r0][k8 + t + 4];
            afH[3] = AsH[r0 + 8][k8 + t + 4]; afL[3] = AsL[r0 + 8][k8 + t + 4];
#pragma unroll
            for (int tj = 0; tj < 4; tj++) {
                int nr = wn * 32 + tj * 8 + g;
                bfH[tj][0] = BsH[nr][k8 + t];
                bfH[tj][1] = BsH[nr][k8 + t + 4];
                if (TERMS == 3) {
                    bfL[tj][0] = BsL[nr][k8 + t];
                    bfL[tj][1] = BsL[nr][k8 + t + 4];
                }
            }
#pragma unroll
            for (int tj = 0; tj < 4; tj++) {
                mma_tf32(acc[tj], afH, bfH[tj]);
                mma_tf32(acc[tj], afL, bfH[tj]);
                if (TERMS == 3) mma_tf32(acc[tj], afH, bfL[tj]);
            }
        }
        if (it < 7) stage(1 - cur);
        __syncthreads();
    }
    const float* dsum = g_sacc + (size_t)NB * NH;
    {
        int r0 = bm + wm * 16 + g;
        float invl = 1.f, invh = 1.f;
        if (SCALE) {
            float dv0 = dsum[r0];
            float dv1 = dsum[r0 + 8];
            invl = dv0 > 0.f ? 1.f / dv0 : 0.f;
            invh = dv1 > 0.f ? 1.f / dv1 : 0.f;
        }
#pragma unroll
        for (int tj = 0; tj < 4; tj++) {
            int col = bn + wn * 32 + tj * 8 + 2 * t;
            float b0 = bias[col], b1 = bias[col + 1];
            float c0 = acc[tj][0] * invl + b0;
            float c1 = acc[tj][1] * invl + b1;
            float c2 = acc[tj][2] * invh + b0;
            float c3 = acc[tj][3] * invh + b1;
            if (ACT) {
                c0 = c0 > 0.f ? c0 : expm1f(c0);
                c1 = c1 > 0.f ? c1 : expm1f(c1);
                c2 = c2 > 0.f ? c2 : expm1f(c2);
                c3 = c3 > 0.f ? c3 : expm1f(c3);
            }
            *reinterpret_cast<float2*>(&C[(size_t)r0 * N + col]) = make_float2(c0, c1);
            *reinterpret_cast<float2*>(&C[(size_t)(r0 + 8) * N + col]) = make_float2(c2, c3);
        }
    }
}

// h = elu((sacc/dsum) @ W + bias_gat) [64 blocks] + gh = out @ W_hh^T + b_hh [192]
__global__ void __launch_bounds__(256, 3)
gemm_h_gh_kernel(const float* __restrict__ bias_gat, const float* __restrict__ b_hh) {
    extern __shared__ __align__(16) unsigned dsm[];
    int bid = blockIdx.x;
    if (bid < 64)
        gemm_nt<2, 1, 1>(dsm, g_sacc, g_WTH, g_WTL, bias_gat, g_h, NH,
                         (bid >> 2) * 64, (bid & 3) * 64);
    else {
        int b2 = bid - 64;
        gemm_nt<2, 0, 0>(dsm, g_out, g_WhhH, g_WhhL, b_hh, g_gh, G3H,
                         (b2 / 12) * 64, (b2 % 12) * 64);
    }
}

__global__ void __launch_bounds__(256, 3)
gemm_gi_kernel(const float* __restrict__ b_ih) {
    extern __shared__ __align__(16) unsigned dsm[];
    gemm_nt<2, 0, 0>(dsm, g_h, g_WihH, g_WihL, b_ih, g_gi, G3H,
                     (blockIdx.x / 12) * 64, (blockIdx.x % 12) * 64);
}

__global__ void __launch_bounds__(256)
gemm_final_kernel(const float* __restrict__ b_lin, float* __restrict__ out) {
    extern __shared__ __align__(16) unsigned dsm[];
    gemm_nt<3, 0, 0>(dsm, g_out, g_WlinTH, g_WlinTL, b_lin, out, NOUT,
                     (blockIdx.x >> 1) * 64, (blockIdx.x & 1) * 64);
}

// ------------- GRU elementwise update (in place) + zero sacc for next t ----------
__global__ void gru_kernel() {
    int idx = blockIdx.x * blockDim.x + threadIdx.x;   // 256 blocks x 256 = 65536
    int b = idx >> 6, h4 = idx & 63;
    const float4* gi4 = reinterpret_cast<const float4*>(g_gi) + (size_t)b * (G3H / 4);
    const float4* gh4 = reinterpret_cast<const float4*>(g_gh) + (size_t)b * (G3H / 4);
    float4 gir = gi4[h4], giz = gi4[64 + h4], gin = gi4[128 + h4];
    float4 ghr = gh4[h4], ghz = gh4[64 + h4], ghn = gh4[128 + h4];
    float4* out4 = reinterpret_cast<float4*>(g_out) + idx;
    float4 o = *out4;
    float4 res;
    {
        float r = sigmoidf_(gir.x + ghr.x), z = sigmoidf_(giz.x + ghz.x);
        float nn = tanhf(gin.x + r * ghn.x);
        float v = (1.f - z) * nn + z * o.x; res.x = v * sigmoidf_(v);
    }
    {
        float r = sigmoidf_(gir.y + ghr.y), z = sigmoidf_(giz.y + ghz.y);
        float nn = tanhf(gin.y + r * ghn.y);
        float v = (1.f - z) * nn + z * o.y; res.y = v * sigmoidf_(v);
    }
    {
        float r = sigmoidf_(gir.z + ghr.z), z = sigmoidf_(giz.z + ghz.z);
        float nn = tanhf(gin.z + r * ghn.z);
        float v = (1.f - z) * nn + z * o.z; res.z = v * sigmoidf_(v);
    }
    {
        float r = sigmoidf_(gir.w + ghr.w), z = sigmoidf_(giz.w + ghz.w);
        float nn = tanhf(gin.w + r * ghn.w);
        float v = (1.f - z) * nn + z * o.w; res.w = v * sigmoidf_(v);
    }
    *out4 = res;
    float4 zz = make_float4(0.f, 0.f, 0.f, 0.f);
    float4* s4 = reinterpret_cast<float4*>(g_sacc);
    for (int i = idx; i < (NB * NH + NB) / 4; i += 65536) s4[i] = zz;
}

// ---------------- launch (single stream) ----------------
extern "C" void kernel_launch(void* const* d_in, const int* in_sizes, int n_in,
                              void* d_out, int out_size) {
    const float* x        = (const float*)d_in[0];
    const int*   batch    = (const int*)d_in[1];
    const float* W        = (const float*)d_in[2];
    const float* att_src  = (const float*)d_in[3];
    const float* att_dst  = (const float*)d_in[4];
    const float* bias_gat = (const float*)d_in[5];
    const float* W_ih     = (const float*)d_in[6];
    const float* W_hh     = (const float*)d_in[7];
    const float* b_ih     = (const float*)d_in[8];
    const float* b_hh     = (const float*)d_in[9];
    const float* W_lin    = (const float*)d_in[10];
    const float* b_lin    = (const float*)d_in[11];
    float*       out      = (float*)d_out;

    const int n = in_sizes[1];
    const int nch = (n + CH - 1) / CH;
    const float4* x4 = reinterpret_cast<const float4*>(x);

    cudaFuncSetAttribute(gemm_h_gh_kernel,
                         cudaFuncAttributeMaxDynamicSharedMemorySize, SMEM2);
    cudaFuncSetAttribute(gemm_gi_kernel,
                         cudaFuncAttributeMaxDynamicSharedMemorySize, SMEM2);
    cudaFuncSetAttribute(gemm_final_kernel,
                         cudaFuncAttributeMaxDynamicSharedMemorySize, SMEM3);

    prep_kernel<<<704, 256>>>(W, att_src, att_dst, W_lin, W_ih, W_hh);
    phaseA_kernel<<<nch, 256>>>(x4, batch, n);

    for (int t = 0; t < 2; t++) {
        attnpool_kernel<<<nch, 256>>>(batch, n);
        gemm_h_gh_kernel<<<256, 256, SMEM2>>>(bias_gat, b_hh);
        gemm_gi_kernel<<<192, 256, SMEM2>>>(b_ih);
        gru_kernel<<<256, 256>>>();
    }

    gemm_final_kernel<<<32, 256, SMEM3>>>(b_lin, out);
}